// round 15
// baseline (speedup 1.0000x reference)
#include <cuda_runtime.h>
#include <math.h>

#define U_N 50000
#define B_N 20000
#define I_N 100000
#define D 64
#define BATCH 2048
#define INVTAU 4.0f
#define LAM1 0.04f
#define LAM2 1e-5f
#define XI (1.0f/3.0f)
#define DB (D * BATCH)

// ---------------- static device workspace (no allocs allowed) ----------------
__device__ float g_fUB[(U_N + B_N) * D];
__device__ float g_tUB[(U_N + B_N) * D];
__device__ float g_fUI[(U_N + I_N) * D];
__device__ float g_tUI[(U_N + I_N) * D];
__device__ float g_fBI[(B_N + I_N) * D];
__device__ float g_tBI[(B_N + I_N) * D];
__device__ float g_tAB[B_N * D];             // biagg scratch (stream 1)
__device__ float g_tAU[U_N * D];             // uiagg scratch (stream 2)
__device__ float g_UB [(U_N + B_N) * D];
__device__ float g_UI [(U_N + I_N) * D];
__device__ float g_BI [(B_N + I_N) * D];
__device__ float g_UIb[B_N * D];
__device__ float g_BIu[U_N * D];
__device__ float g_P  [6 * DB];              // normalized CL matrices, k-major: [p][k][i]
__device__ float g_rs [6 * BATCH];           // intra row sums (zero-init; fin re-zeroes)
__device__ float g_acc[4];                   // 0: sum logsigmoid, 1: reg, 2: cl

__constant__ int c_pa[6] = {0,0,1,3,3,4};
__constant__ int c_pb[6] = {1,2,2,4,5,5};

// ---------------- static streams/events (created once) ----------------
namespace {
struct StreamHolder {
    cudaStream_t s1 = 0, s2 = 0;
    cudaEvent_t  f = 0, e1 = 0, e2 = 0;
    StreamHolder() {
        cudaStreamCreateWithFlags(&s1, cudaStreamNonBlocking);
        cudaStreamCreateWithFlags(&s2, cudaStreamNonBlocking);
        cudaEventCreateWithFlags(&f,  cudaEventDisableTiming);
        cudaEventCreateWithFlags(&e1, cudaEventDisableTiming);
        cudaEventCreateWithFlags(&e2, cudaEventDisableTiming);
    }
};
StreamHolder g_sh;
}

// ---------------- small helpers ----------------
__device__ __forceinline__ float warp_sum(float v) {
#pragma unroll
    for (int o = 16; o; o >>= 1) v += __shfl_xor_sync(0xffffffffu, v, o);
    return v;
}
__device__ __forceinline__ float sgn(float x) {
    return (x > 0.f) ? 1.f : ((x < 0.f) ? -1.f : 0.f);
}
__device__ __forceinline__ void red4(float* p, float4 o) {
    asm volatile("red.global.add.v4.f32 [%0], {%1,%2,%3,%4};"
                 :: "l"(p), "f"(o.x), "f"(o.y), "f"(o.z), "f"(o.w) : "memory");
}

// ---------------- kernels ----------------

__global__ void k_init(const float* __restrict__ A, const float* __restrict__ Bf,
                       int nA, int n, float* feats, float* outb) {
    int i = blockIdx.x * blockDim.x + threadIdx.x;
    if (i >= n * D) return;
    float v = (i < nA * D) ? A[i] : Bf[i - nA * D];
    feats[i] = v;
    outb[i]  = v * XI;
}

// fp32 COO spmm: 16 threads/chunk, 4 edges/thread (MLP=4). Proven floor.
__global__ void k_spmm(const int* __restrict__ rows, const int* __restrict__ cols,
                       const float* __restrict__ vals, const float* __restrict__ x,
                       float* out, int nE) {
    int t = blockIdx.x * blockDim.x + threadIdx.x;
    int g = t >> 4;
    int c = t & 15;
    int e0 = g * 4;
    if (e0 >= nE) return;
    int nv = nE - e0;

    int   r[4], cc[4];
    float v[4];
    if (nv >= 4) {
        int4   r4 = __ldg((const int4*)(rows + e0));
        int4   c4 = __ldg((const int4*)(cols + e0));
        float4 v4 = __ldg((const float4*)(vals + e0));
        r[0]=r4.x; r[1]=r4.y; r[2]=r4.z; r[3]=r4.w;
        cc[0]=c4.x; cc[1]=c4.y; cc[2]=c4.z; cc[3]=c4.w;
        v[0]=v4.x; v[1]=v4.y; v[2]=v4.z; v[3]=v4.w;
    } else {
#pragma unroll
        for (int k = 0; k < 4; ++k) {
            int e = e0 + ((k < nv) ? k : (nv - 1));
            r[k]  = __ldg(rows + e);
            cc[k] = __ldg(cols + e);
            v[k]  = __ldg(vals + e);
        }
    }
    float4 a[4];
#pragma unroll
    for (int k = 0; k < 4; ++k)
        a[k] = __ldg((const float4*)(x + (size_t)cc[k] * D) + c);
#pragma unroll
    for (int k = 0; k < 4; ++k) {
        if (k < nv) {
            red4(out + (size_t)r[k] * D + c * 4,
                 make_float4(v[k]*a[k].x, v[k]*a[k].y, v[k]*a[k].z, v[k]*a[k].w));
        }
    }
}

__global__ void k_prop_row(const float* __restrict__ tmp, const float* __restrict__ noise,
                           float* feats, float* outb, int n, float ups) {
    int row = blockIdx.x * 8 + (threadIdx.x >> 5);
    int lane = threadIdx.x & 31;
    if (row >= n) return;
    size_t off = (size_t)row * D + lane * 2;
    float2 t  = *(const float2*)(tmp + off);
    float2 nz = *(const float2*)(noise + off);
    float ns = warp_sum(nz.x * nz.x + nz.y * nz.y);
    float ninv = ups / fmaxf(sqrtf(ns), 1e-12f);
    float fx = t.x + sgn(t.x) * nz.x * ninv;
    float fy = t.y + sgn(t.y) * nz.y * ninv;
    float fs = warp_sum(fx * fx + fy * fy);
    float finv = XI / fmaxf(sqrtf(fs), 1e-12f);
    float2 ob = *(float2*)(outb + off);
    ob.x += fx * finv;
    ob.y += fy * finv;
    *(float2*)(outb + off) = ob;
    *(float2*)(feats + off) = make_float2(fx, fy);
}

__global__ void k_agg_row(const float* __restrict__ tmp, const float* __restrict__ noise,
                          float* outb, int n, float ups) {
    int row = blockIdx.x * 8 + (threadIdx.x >> 5);
    int lane = threadIdx.x & 31;
    if (row >= n) return;
    size_t off = (size_t)row * D + lane * 2;
    float2 t  = *(const float2*)(tmp + off);
    float2 nz = *(const float2*)(noise + off);
    float ns = warp_sum(nz.x * nz.x + nz.y * nz.y);
    float ninv = ups / fmaxf(sqrtf(ns), 1e-12f);
    float fx = t.x + sgn(t.x) * nz.x * ninv;
    float fy = t.y + sgn(t.y) * nz.y * ninv;
    *(float2*)(outb + off) = make_float2(fx, fy);
}

__global__ void k_sumsq(const float* __restrict__ x, int n, float* acc) {
    float s = 0.f;
    for (int i = blockIdx.x * blockDim.x + threadIdx.x; i < n; i += gridDim.x * blockDim.x) {
        float v = x[i];
        s += v * v;
    }
    s = warp_sum(s);
    __shared__ float sm[8];
    if ((threadIdx.x & 31) == 0) sm[threadIdx.x >> 5] = s;
    __syncthreads();
    if (threadIdx.x == 0) {
        float tt = 0.f;
#pragma unroll
        for (int i = 0; i < 8; ++i) tt += sm[i];
        atomicAdd(acc, tt);
    }
}

__global__ void k_bpr(const int* __restrict__ users, const int* __restrict__ bundles,
                      const float* __restrict__ UIu, const float* __restrict__ BIu,
                      const float* __restrict__ UIb, const float* __restrict__ BIb,
                      float* acc) {
    int i = blockIdx.x * 8 + (threadIdx.x >> 5);
    int lane = threadIdx.x & 31;
    if (i >= BATCH) return;
    int u  = users[i];
    int bp = bundles[2 * i];
    int bn = bundles[2 * i + 1];
    size_t uo = (size_t)u * D + lane * 2;
    float2 a1 = *(const float2*)(UIu + uo);
    float2 a2 = *(const float2*)(BIu + uo);
    float ux = 0.5f * (a1.x + a2.x), uy = 0.5f * (a1.y + a2.y);
    size_t po = (size_t)bp * D + lane * 2;
    float2 p1 = *(const float2*)(UIb + po);
    float2 p2 = *(const float2*)(BIb + po);
    float px = 0.5f * (p1.x + p2.x), py = 0.5f * (p1.y + p2.y);
    size_t no = (size_t)bn * D + lane * 2;
    float2 q1 = *(const float2*)(UIb + no);
    float2 q2 = *(const float2*)(BIb + no);
    float qx = 0.5f * (q1.x + q2.x), qy = 0.5f * (q1.y + q2.y);
    float dp = warp_sum(ux * px + uy * py);
    float dn = warp_sum(ux * qx + uy * qy);
    if (lane == 0) {
        float x = dp - dn;
        float ls = (x >= 0.f) ? -log1pf(expf(-x)) : (x - log1pf(expf(x)));
        atomicAdd(acc, ls);
    }
}

// single-matrix gather + row-normalize into k-major dstP[k][i]
__global__ void k_gather1(const int* __restrict__ ids, int stride,
                          const float* __restrict__ src, float* __restrict__ dstP) {
    int i = blockIdx.x * 8 + (threadIdx.x >> 5);
    int lane = threadIdx.x & 31;
    if (i >= BATCH) return;
    int r0 = ids[i * stride];
    const float* s = src + (size_t)r0 * D;
    float2 v = *(const float2*)(s + lane * 2);
    float ss = warp_sum(v.x * v.x + v.y * v.y);
    float inv = 1.f / fmaxf(sqrtf(ss), 1e-12f);
    dstP[(size_t)(2 * lane) * BATCH + i]     = v.x * inv;
    dstP[(size_t)(2 * lane + 1) * BATCH + i] = v.y * inv;
}

// 6 inter losses: S = P@Q^T/tau, loss_i = log(sum_j exp(S_ij)) - S_ii
// 32 i-rows x 128 j-rows per block (grid 64 x 6): 2x8 register tile.
// Smaller per-block critical path + better SM load balance than 64-row tiles.
__global__ void __launch_bounds__(256) k_cl_inter(const float* __restrict__ P, float* acc) {
    __shared__ float Ps[64 * 32];    // [k][i] 8KB
    __shared__ float Qs[64 * 128];   // [k][j] 32KB
    int p  = blockIdx.y;
    int bi = blockIdx.x;             // 0..63, 32 i-rows per block
    int tid = threadIdx.x;
    int tx = tid & 15;               // j sub-tile (8 cols each)
    int ty = tid >> 4;               // i sub-tile (2 rows each)
    const float* Pg = P + (size_t)c_pa[p] * DB;
    const float* Qg = P + (size_t)c_pb[p] * DB;
    for (int idx = tid; idx < 64 * 8; idx += 256) {
        int k = idx >> 3, c4 = idx & 7;
        *(float4*)(Ps + k * 32 + c4 * 4) = *(const float4*)(Pg + (size_t)k * BATCH + bi * 32 + c4 * 4);
    }
    float rs[2] = {0.f, 0.f};
    float sii[2] = {0.f, 0.f};
    int ibase = bi * 32 + ty * 2;
    for (int jt = 0; jt < 16; ++jt) {
        __syncthreads();
        for (int idx = tid; idx < 64 * 32; idx += 256) {
            int k = idx >> 5, c4 = idx & 31;
            *(float4*)(Qs + k * 128 + c4 * 4) = *(const float4*)(Qg + (size_t)k * BATCH + jt * 128 + c4 * 4);
        }
        __syncthreads();
        float av[2][8];
#pragma unroll
        for (int r = 0; r < 2; ++r)
#pragma unroll
            for (int c = 0; c < 8; ++c) av[r][c] = 0.f;
#pragma unroll 8
        for (int k = 0; k < 64; ++k) {
            float a[2], b[8];
            *(float2*)a       = *(const float2*)(Ps + k * 32 + ty * 2);
            *(float4*)b       = *(const float4*)(Qs + k * 128 + tx * 8);
            *(float4*)(b + 4) = *(const float4*)(Qs + k * 128 + tx * 8 + 4);
#pragma unroll
            for (int r = 0; r < 2; ++r)
#pragma unroll
                for (int c = 0; c < 8; ++c) av[r][c] += a[r] * b[c];
        }
        int jbase = jt * 128 + tx * 8;
#pragma unroll
        for (int r = 0; r < 2; ++r) {
#pragma unroll
            for (int c = 0; c < 8; ++c) {
                float s = av[r][c] * INVTAU;
                if (jbase + c == ibase + r) sii[r] = s;
                rs[r] += __expf(s);
            }
        }
    }
#pragma unroll
    for (int r = 0; r < 2; ++r)
#pragma unroll
        for (int o = 1; o < 16; o <<= 1) rs[r] += __shfl_xor_sync(0xffffffffu, rs[r], o);
    float part = 0.f;
#pragma unroll
    for (int r = 0; r < 2; ++r) {
        int ig = ibase + r;
        int tx_d = (ig & 127) >> 3;
        int srcLane = ((ty & 1) << 4) | tx_d;
        float s = __shfl_sync(0xffffffffu, sii[r], srcLane);
        if (tx == 0) part += logf(rs[r]) - s;
    }
    if (tx == 0) atomicAdd(acc, (LAM1 * 0.5f / (float)BATCH) * part);
}

// single intra loss via symmetry (tile pairs ta<=tb) — R9-proven body, per-matrix.
__global__ void __launch_bounds__(256) k_cl_intra1(const float* __restrict__ Pg,
                                                   float* __restrict__ rsp) {
    __shared__ float Pa[32 * 128];
    __shared__ float Pb[32 * 128];
    __shared__ float sm_col[16 * 128];
    int rem = blockIdx.x;
    int ta = 0;
    while (rem >= 16 - ta) { rem -= 16 - ta; ++ta; }
    int tb = ta + rem;
    int tid = threadIdx.x;
    int tx = tid & 15;
    int ty = tid >> 4;

    float av[8][8];
#pragma unroll
    for (int r = 0; r < 8; ++r)
#pragma unroll
        for (int c = 0; c < 8; ++c) av[r][c] = 0.f;

#pragma unroll
    for (int kc = 0; kc < 2; ++kc) {
        __syncthreads();
        for (int idx = tid; idx < 32 * 32; idx += 256) {
            int k = idx >> 5, c4 = idx & 31;
            const float* src = Pg + (size_t)(kc * 32 + k) * BATCH;
            *(float4*)(Pa + k * 128 + c4 * 4) = *(const float4*)(src + ta * 128 + c4 * 4);
            *(float4*)(Pb + k * 128 + c4 * 4) = *(const float4*)(src + tb * 128 + c4 * 4);
        }
        __syncthreads();
#pragma unroll 8
        for (int k = 0; k < 32; ++k) {
            float a[8], b[8];
            *(float4*)a       = *(const float4*)(Pa + k * 128 + ty * 8);
            *(float4*)(a + 4) = *(const float4*)(Pa + k * 128 + ty * 8 + 4);
            *(float4*)b       = *(const float4*)(Pb + k * 128 + tx * 8);
            *(float4*)(b + 4) = *(const float4*)(Pb + k * 128 + tx * 8 + 4);
#pragma unroll
            for (int r = 0; r < 8; ++r)
#pragma unroll
                for (int c = 0; c < 8; ++c) av[r][c] += a[r] * b[c];
        }
    }

    float rsum[8], csum[8];
#pragma unroll
    for (int r = 0; r < 8; ++r) rsum[r] = 0.f;
#pragma unroll
    for (int c = 0; c < 8; ++c) csum[c] = 0.f;
#pragma unroll
    for (int r = 0; r < 8; ++r)
#pragma unroll
        for (int c = 0; c < 8; ++c) {
            float e = __expf(av[r][c] * INVTAU);
            rsum[r] += e;
            csum[c] += e;
        }
#pragma unroll
    for (int r = 0; r < 8; ++r)
#pragma unroll
        for (int o = 1; o < 16; o <<= 1) rsum[r] += __shfl_xor_sync(0xffffffffu, rsum[r], o);
    if (tx == 0) {
#pragma unroll
        for (int r = 0; r < 8; ++r)
            atomicAdd(rsp + ta * 128 + ty * 8 + r, rsum[r]);
    }
    if (ta != tb) {
        __syncthreads();
        *(float4*)(sm_col + ty * 128 + tx * 8)     = *(float4*)csum;
        *(float4*)(sm_col + ty * 128 + tx * 8 + 4) = *(float4*)(csum + 4);
        __syncthreads();
        if (tid < 128) {
            float s = 0.f;
#pragma unroll
            for (int t = 0; t < 16; ++t) s += sm_col[t * 128 + tid];
            atomicAdd(rsp + tb * 128 + tid, s);
        }
    }
}

__global__ void k_cl_fin(float* __restrict__ rs, float* acc) {
    int i = blockIdx.x * blockDim.x + threadIdx.x;
    float part = 0.f;
    if (i < 6 * BATCH) {
        float v = rs[i];
        rs[i] = 0.f;
        part = logf(v) - INVTAU;
    }
    part = warp_sum(part);
    __shared__ float sm[8];
    if ((threadIdx.x & 31) == 0) sm[threadIdx.x >> 5] = part;
    __syncthreads();
    if (threadIdx.x == 0) {
        float tt = 0.f;
#pragma unroll
        for (int k = 0; k < 8; ++k) tt += sm[k];
        atomicAdd(acc, (LAM1 * 0.5f / (float)BATCH) * tt);
    }
}

__global__ void k_final(const float* __restrict__ acc, float* out, int out_size) {
    if (threadIdx.x == 0) {
        out[0] = -acc[0] / (float)BATCH + LAM2 * acc[1];
        if (out_size > 1) out[1] = acc[2];
    }
}

// ---------------- host orchestration ----------------
extern "C" void kernel_launch(void* const* d_in, const int* in_sizes, int n_in,
                              void* d_out, int out_size) {
    const float* uf  = (const float*)d_in[0];
    const float* bfe = (const float*)d_in[1];
    const float* itf = (const float*)d_in[2];
    const int*   ub_r = (const int*)d_in[3];
    const int*   ub_c = (const int*)d_in[4];
    const float* ub_v = (const float*)d_in[5];
    const int*   ui_r = (const int*)d_in[6];
    const int*   ui_c = (const int*)d_in[7];
    const float* ui_v = (const float*)d_in[8];
    const int*   bi_r = (const int*)d_in[9];
    const int*   bi_c = (const int*)d_in[10];
    const float* bi_v = (const float*)d_in[11];
    const int*   ba_r = (const int*)d_in[12];
    const int*   ba_c = (const int*)d_in[13];
    const float* ba_v = (const float*)d_in[14];
    const int*   ua_r = (const int*)d_in[15];
    const int*   ua_c = (const int*)d_in[16];
    const float* ua_v = (const float*)d_in[17];
    const float* n_UB  = (const float*)d_in[18];
    const float* n_UI  = (const float*)d_in[19];
    const float* n_BI  = (const float*)d_in[20];
    const float* n_aBI = (const float*)d_in[21];
    const float* n_aUI = (const float*)d_in[22];
    const int* users   = (const int*)d_in[23];
    const int* bundles = (const int*)d_in[24];

    int nUB = in_sizes[3];
    int nUI = in_sizes[6];
    int nBI = in_sizes[9];
    int nBA = in_sizes[12];
    int nUA = in_sizes[15];

    float *fUB, *tUB, *fUI, *tUI, *fBI, *tBI, *tAB, *tAU;
    float *pUB, *pUI, *pBI, *pUIb, *pBIu, *pP, *prs, *acc;
    cudaGetSymbolAddress((void**)&fUB, g_fUB);
    cudaGetSymbolAddress((void**)&tUB, g_tUB);
    cudaGetSymbolAddress((void**)&fUI, g_fUI);
    cudaGetSymbolAddress((void**)&tUI, g_tUI);
    cudaGetSymbolAddress((void**)&fBI, g_fBI);
    cudaGetSymbolAddress((void**)&tBI, g_tBI);
    cudaGetSymbolAddress((void**)&tAB, g_tAB);
    cudaGetSymbolAddress((void**)&tAU, g_tAU);
    cudaGetSymbolAddress((void**)&pUB, g_UB);
    cudaGetSymbolAddress((void**)&pUI, g_UI);
    cudaGetSymbolAddress((void**)&pBI, g_BI);
    cudaGetSymbolAddress((void**)&pUIb, g_UIb);
    cudaGetSymbolAddress((void**)&pBIu, g_BIu);
    cudaGetSymbolAddress((void**)&pP,  g_P);
    cudaGetSymbolAddress((void**)&prs, g_rs);
    cudaGetSymbolAddress((void**)&acc, g_acc);

    cudaStream_t s0 = 0;
    cudaStream_t s1 = g_sh.s1, s2 = g_sh.s2;

    cudaMemsetAsync(acc, 0, 4 * sizeof(float), s0);

    cudaEventRecord(g_sh.f, s0);
    cudaStreamWaitEvent(s1, g_sh.f, 0);
    cudaStreamWaitEvent(s2, g_sh.f, 0);

    auto spmm = [&](cudaStream_t st, const int* r, const int* c, const float* v,
                    int nE, const float* x, float* out) {
        long long thr = (long long)((nE + 3) / 4) * 16;
        int blocks = (int)((thr + 255) / 256);
        k_spmm<<<blocks, 256, 0, st>>>(r, c, v, x, out, nE);
    };

    auto propagate = [&](cudaStream_t st, float* feats, float* tmp,
                         const int* r, const int* c, const float* v, int nE,
                         const float* A, const float* Bf, int nA, int n,
                         const float* noise, float ups, float* outb) {
        int nd = n * D;
        k_init<<<(nd + 255) / 256, 256, 0, st>>>(A, Bf, nA, n, feats, outb);
        for (int l = 0; l < 2; ++l) {
            cudaMemsetAsync(tmp, 0, (size_t)nd * sizeof(float), st);
            spmm(st, r, c, v, nE, feats, tmp);
            k_prop_row<<<(n + 7) / 8, 256, 0, st>>>(tmp, noise + (size_t)l * nd, feats, outb, n, ups);
        }
    };

    int gb = (BATCH + 7) / 8;   // gather/bpr grid

    // s0: UB chain, then regularizer, then UB-dependent CL work (p0, p3)
    propagate(s0, fUB, tUB, ub_r, ub_c, ub_v, nUB, uf,  bfe, U_N, U_N + B_N, n_UB, 0.1f, pUB);
    k_sumsq<<<592, 256, 0, s0>>>(uf,  U_N * D, acc + 1);
    k_sumsq<<<592, 256, 0, s0>>>(bfe, B_N * D, acc + 1);
    k_sumsq<<<592, 256, 0, s0>>>(itf, I_N * D, acc + 1);
    k_gather1<<<gb, 256, 0, s0>>>(users,   1, pUB,                      pP + 0 * DB);
    k_gather1<<<gb, 256, 0, s0>>>(bundles, 2, pUB + (size_t)U_N * D,    pP + 3 * DB);
    k_cl_intra1<<<136, 256, 0, s0>>>(pP + 0 * DB, prs + 0 * BATCH);
    k_cl_intra1<<<136, 256, 0, s0>>>(pP + 3 * DB, prs + 3 * BATCH);

    // s1: UI chain, biagg -> UIb, then UI-dependent CL work (p1, p4)
    propagate(s1, fUI, tUI, ui_r, ui_c, ui_v, nUI, uf,  itf, U_N, U_N + I_N, n_UI, 0.1f, pUI);
    cudaMemsetAsync(tAB, 0, (size_t)B_N * D * sizeof(float), s1);
    spmm(s1, ba_r, ba_c, ba_v, nBA, pUI + (size_t)U_N * D, tAB);
    k_agg_row<<<(B_N + 7) / 8, 256, 0, s1>>>(tAB, n_aBI, pUIb, B_N, 0.1f);
    k_gather1<<<gb, 256, 0, s1>>>(users,   1, pUI,  pP + 1 * DB);
    k_cl_intra1<<<136, 256, 0, s1>>>(pP + 1 * DB, prs + 1 * BATCH);
    k_gather1<<<gb, 256, 0, s1>>>(bundles, 2, pUIb, pP + 4 * DB);
    k_cl_intra1<<<136, 256, 0, s1>>>(pP + 4 * DB, prs + 4 * BATCH);
    cudaEventRecord(g_sh.e1, s1);

    // s2: BI chain, uiagg -> BIu, then BI-dependent CL work (p5, p2)
    propagate(s2, fBI, tBI, bi_r, bi_c, bi_v, nBI, bfe, itf, B_N, B_N + I_N, n_BI, 0.1f, pBI);
    k_gather1<<<gb, 256, 0, s2>>>(bundles, 2, pBI,  pP + 5 * DB);
    k_cl_intra1<<<136, 256, 0, s2>>>(pP + 5 * DB, prs + 5 * BATCH);
    cudaMemsetAsync(tAU, 0, (size_t)U_N * D * sizeof(float), s2);
    spmm(s2, ua_r, ua_c, ua_v, nUA, pBI + (size_t)B_N * D, tAU);
    k_agg_row<<<(U_N + 7) / 8, 256, 0, s2>>>(tAU, n_aUI, pBIu, U_N, 0.1f);
    k_gather1<<<gb, 256, 0, s2>>>(users,   1, pBIu, pP + 2 * DB);
    k_cl_intra1<<<136, 256, 0, s2>>>(pP + 2 * DB, prs + 2 * BATCH);
    cudaEventRecord(g_sh.e2, s2);

    // join
    cudaStreamWaitEvent(s0, g_sh.e1, 0);
    cudaStreamWaitEvent(s0, g_sh.e2, 0);

    // BPR + inter losses + finish
    k_bpr<<<gb, 256, 0, s0>>>(users, bundles, pUI, pBIu, pUIb, pBI, acc);
    k_cl_inter<<<dim3(64, 6), 256, 0, s0>>>(pP, acc + 2);
    k_cl_fin<<<(6 * BATCH + 255) / 256, 256, 0, s0>>>(prs, acc + 2);

    k_final<<<1, 1, 0, s0>>>(acc, (float*)d_out, out_size);
}

// round 16
// speedup vs baseline: 1.6136x; 1.6136x over previous
#include <cuda_runtime.h>
#include <math.h>

#define U_N 50000
#define B_N 20000
#define I_N 100000
#define D 64
#define BATCH 2048
#define INVTAU 4.0f
#define LAM1 0.04f
#define LAM2 1e-5f
#define XI (1.0f/3.0f)
#define DB (D * BATCH)

// ---------------- static device workspace (no allocs allowed) ----------------
__device__ float g_fUB[(U_N + B_N) * D];
__device__ float g_tUB[(U_N + B_N) * D];
__device__ float g_fUI[(U_N + I_N) * D];
__device__ float g_tUI[(U_N + I_N) * D];
__device__ float g_fBI[(B_N + I_N) * D];
__device__ float g_tBI[(B_N + I_N) * D];
__device__ float g_tAB[B_N * D];             // biagg scratch (stream 1)
__device__ float g_tAU[U_N * D];             // uiagg scratch (stream 2)
__device__ float g_UB [(U_N + B_N) * D];
__device__ float g_UI [(U_N + I_N) * D];
__device__ float g_BI [(B_N + I_N) * D];
__device__ float g_UIb[B_N * D];
__device__ float g_BIu[U_N * D];
__device__ float g_P  [6 * DB];              // normalized CL matrices, k-major: [p][k][i]
__device__ float g_rs [6 * BATCH];           // intra row sums (zero-init; fin re-zeroes)
__device__ float g_acc[4];                   // 0: sum logsigmoid, 1: reg, 2: cl

__constant__ int c_pa[6] = {0,0,1,3,3,4};
__constant__ int c_pb[6] = {1,2,2,4,5,5};

// ---------------- static streams/events (created once) ----------------
namespace {
struct StreamHolder {
    cudaStream_t s1 = 0, s2 = 0;
    cudaEvent_t  f = 0, e1 = 0, e2 = 0;
    StreamHolder() {
        cudaStreamCreateWithFlags(&s1, cudaStreamNonBlocking);
        cudaStreamCreateWithFlags(&s2, cudaStreamNonBlocking);
        cudaEventCreateWithFlags(&f,  cudaEventDisableTiming);
        cudaEventCreateWithFlags(&e1, cudaEventDisableTiming);
        cudaEventCreateWithFlags(&e2, cudaEventDisableTiming);
    }
};
StreamHolder g_sh;
}

// ---------------- small helpers ----------------
__device__ __forceinline__ float warp_sum(float v) {
#pragma unroll
    for (int o = 16; o; o >>= 1) v += __shfl_xor_sync(0xffffffffu, v, o);
    return v;
}
__device__ __forceinline__ float sgn(float x) {
    return (x > 0.f) ? 1.f : ((x < 0.f) ? -1.f : 0.f);
}
__device__ __forceinline__ void red4(float* p, float4 o) {
    asm volatile("red.global.add.v4.f32 [%0], {%1,%2,%3,%4};"
                 :: "l"(p), "f"(o.x), "f"(o.y), "f"(o.z), "f"(o.w) : "memory");
}

// ---------------- kernels ----------------

__global__ void k_init(const float* __restrict__ A, const float* __restrict__ Bf,
                       int nA, int n, float* feats, float* outb) {
    int i = blockIdx.x * blockDim.x + threadIdx.x;
    if (i >= n * D) return;
    float v = (i < nA * D) ? A[i] : Bf[i - nA * D];
    feats[i] = v;
    outb[i]  = v * XI;
}

// fp32 COO spmm: 16 threads/chunk, 4 edges/thread (MLP=4). Proven floor.
__global__ void k_spmm(const int* __restrict__ rows, const int* __restrict__ cols,
                       const float* __restrict__ vals, const float* __restrict__ x,
                       float* out, int nE) {
    int t = blockIdx.x * blockDim.x + threadIdx.x;
    int g = t >> 4;
    int c = t & 15;
    int e0 = g * 4;
    if (e0 >= nE) return;
    int nv = nE - e0;

    int   r[4], cc[4];
    float v[4];
    if (nv >= 4) {
        int4   r4 = __ldg((const int4*)(rows + e0));
        int4   c4 = __ldg((const int4*)(cols + e0));
        float4 v4 = __ldg((const float4*)(vals + e0));
        r[0]=r4.x; r[1]=r4.y; r[2]=r4.z; r[3]=r4.w;
        cc[0]=c4.x; cc[1]=c4.y; cc[2]=c4.z; cc[3]=c4.w;
        v[0]=v4.x; v[1]=v4.y; v[2]=v4.z; v[3]=v4.w;
    } else {
#pragma unroll
        for (int k = 0; k < 4; ++k) {
            int e = e0 + ((k < nv) ? k : (nv - 1));
            r[k]  = __ldg(rows + e);
            cc[k] = __ldg(cols + e);
            v[k]  = __ldg(vals + e);
        }
    }
    float4 a[4];
#pragma unroll
    for (int k = 0; k < 4; ++k)
        a[k] = __ldg((const float4*)(x + (size_t)cc[k] * D) + c);
#pragma unroll
    for (int k = 0; k < 4; ++k) {
        if (k < nv) {
            red4(out + (size_t)r[k] * D + c * 4,
                 make_float4(v[k]*a[k].x, v[k]*a[k].y, v[k]*a[k].z, v[k]*a[k].w));
        }
    }
}

__global__ void k_prop_row(const float* __restrict__ tmp, const float* __restrict__ noise,
                           float* feats, float* outb, int n, float ups) {
    int row = blockIdx.x * 8 + (threadIdx.x >> 5);
    int lane = threadIdx.x & 31;
    if (row >= n) return;
    size_t off = (size_t)row * D + lane * 2;
    float2 t  = *(const float2*)(tmp + off);
    float2 nz = *(const float2*)(noise + off);
    float ns = warp_sum(nz.x * nz.x + nz.y * nz.y);
    float ninv = ups / fmaxf(sqrtf(ns), 1e-12f);
    float fx = t.x + sgn(t.x) * nz.x * ninv;
    float fy = t.y + sgn(t.y) * nz.y * ninv;
    float fs = warp_sum(fx * fx + fy * fy);
    float finv = XI / fmaxf(sqrtf(fs), 1e-12f);
    float2 ob = *(float2*)(outb + off);
    ob.x += fx * finv;
    ob.y += fy * finv;
    *(float2*)(outb + off) = ob;
    *(float2*)(feats + off) = make_float2(fx, fy);
}

__global__ void k_agg_row(const float* __restrict__ tmp, const float* __restrict__ noise,
                          float* outb, int n, float ups) {
    int row = blockIdx.x * 8 + (threadIdx.x >> 5);
    int lane = threadIdx.x & 31;
    if (row >= n) return;
    size_t off = (size_t)row * D + lane * 2;
    float2 t  = *(const float2*)(tmp + off);
    float2 nz = *(const float2*)(noise + off);
    float ns = warp_sum(nz.x * nz.x + nz.y * nz.y);
    float ninv = ups / fmaxf(sqrtf(ns), 1e-12f);
    float fx = t.x + sgn(t.x) * nz.x * ninv;
    float fy = t.y + sgn(t.y) * nz.y * ninv;
    *(float2*)(outb + off) = make_float2(fx, fy);
}

__global__ void k_sumsq(const float* __restrict__ x, int n, float* acc) {
    float s = 0.f;
    for (int i = blockIdx.x * blockDim.x + threadIdx.x; i < n; i += gridDim.x * blockDim.x) {
        float v = x[i];
        s += v * v;
    }
    s = warp_sum(s);
    __shared__ float sm[8];
    if ((threadIdx.x & 31) == 0) sm[threadIdx.x >> 5] = s;
    __syncthreads();
    if (threadIdx.x == 0) {
        float tt = 0.f;
#pragma unroll
        for (int i = 0; i < 8; ++i) tt += sm[i];
        atomicAdd(acc, tt);
    }
}

__global__ void k_bpr(const int* __restrict__ users, const int* __restrict__ bundles,
                      const float* __restrict__ UIu, const float* __restrict__ BIu,
                      const float* __restrict__ UIb, const float* __restrict__ BIb,
                      float* acc) {
    int i = blockIdx.x * 8 + (threadIdx.x >> 5);
    int lane = threadIdx.x & 31;
    if (i >= BATCH) return;
    int u  = users[i];
    int bp = bundles[2 * i];
    int bn = bundles[2 * i + 1];
    size_t uo = (size_t)u * D + lane * 2;
    float2 a1 = *(const float2*)(UIu + uo);
    float2 a2 = *(const float2*)(BIu + uo);
    float ux = 0.5f * (a1.x + a2.x), uy = 0.5f * (a1.y + a2.y);
    size_t po = (size_t)bp * D + lane * 2;
    float2 p1 = *(const float2*)(UIb + po);
    float2 p2 = *(const float2*)(BIb + po);
    float px = 0.5f * (p1.x + p2.x), py = 0.5f * (p1.y + p2.y);
    size_t no = (size_t)bn * D + lane * 2;
    float2 q1 = *(const float2*)(UIb + no);
    float2 q2 = *(const float2*)(BIb + no);
    float qx = 0.5f * (q1.x + q2.x), qy = 0.5f * (q1.y + q2.y);
    float dp = warp_sum(ux * px + uy * py);
    float dn = warp_sum(ux * qx + uy * qy);
    if (lane == 0) {
        float x = dp - dn;
        float ls = (x >= 0.f) ? -log1pf(expf(-x)) : (x - log1pf(expf(x)));
        atomicAdd(acc, ls);
    }
}

// single-matrix gather + row-normalize into k-major dstP[k][i]
__global__ void k_gather1(const int* __restrict__ ids, int stride,
                          const float* __restrict__ src, float* __restrict__ dstP) {
    int i = blockIdx.x * 8 + (threadIdx.x >> 5);
    int lane = threadIdx.x & 31;
    if (i >= BATCH) return;
    int r0 = ids[i * stride];
    const float* s = src + (size_t)r0 * D;
    float2 v = *(const float2*)(s + lane * 2);
    float ss = warp_sum(v.x * v.x + v.y * v.y);
    float inv = 1.f / fmaxf(sqrtf(ss), 1e-12f);
    dstP[(size_t)(2 * lane) * BATCH + i]     = v.x * inv;
    dstP[(size_t)(2 * lane + 1) * BATCH + i] = v.y * inv;
}

// 6 inter losses: S = P@Q^T/tau, loss_i = log(sum_j exp(S_ij)) - S_ii
__global__ void __launch_bounds__(256) k_cl_inter(const float* __restrict__ P, float* acc) {
    __shared__ float Ps[64 * 64];
    __shared__ float Qs[64 * 128];
    int p  = blockIdx.y;
    int bi = blockIdx.x;
    int tid = threadIdx.x;
    int tx = tid & 15;
    int ty = tid >> 4;
    const float* Pg = P + (size_t)c_pa[p] * DB;
    const float* Qg = P + (size_t)c_pb[p] * DB;
    for (int idx = tid; idx < 64 * 16; idx += 256) {
        int k = idx >> 4, c4 = idx & 15;
        *(float4*)(Ps + k * 64 + c4 * 4) = *(const float4*)(Pg + (size_t)k * BATCH + bi * 64 + c4 * 4);
    }
    float rs[4] = {0.f, 0.f, 0.f, 0.f};
    float sii[4] = {0.f, 0.f, 0.f, 0.f};
    int ibase = bi * 64 + ty * 4;
    for (int jt = 0; jt < 16; ++jt) {
        __syncthreads();
        for (int idx = tid; idx < 64 * 32; idx += 256) {
            int k = idx >> 5, c4 = idx & 31;
            *(float4*)(Qs + k * 128 + c4 * 4) = *(const float4*)(Qg + (size_t)k * BATCH + jt * 128 + c4 * 4);
        }
        __syncthreads();
        float av[4][8];
#pragma unroll
        for (int r = 0; r < 4; ++r)
#pragma unroll
            for (int c = 0; c < 8; ++c) av[r][c] = 0.f;
#pragma unroll 8
        for (int k = 0; k < 64; ++k) {
            float a[4], b[8];
            *(float4*)a       = *(const float4*)(Ps + k * 64 + ty * 4);
            *(float4*)b       = *(const float4*)(Qs + k * 128 + tx * 8);
            *(float4*)(b + 4) = *(const float4*)(Qs + k * 128 + tx * 8 + 4);
#pragma unroll
            for (int r = 0; r < 4; ++r)
#pragma unroll
                for (int c = 0; c < 8; ++c) av[r][c] += a[r] * b[c];
        }
        int jbase = jt * 128 + tx * 8;
#pragma unroll
        for (int r = 0; r < 4; ++r) {
#pragma unroll
            for (int c = 0; c < 8; ++c) {
                float s = av[r][c] * INVTAU;
                if (jbase + c == ibase + r) sii[r] = s;
                rs[r] += __expf(s);
            }
        }
    }
#pragma unroll
    for (int r = 0; r < 4; ++r)
#pragma unroll
        for (int o = 1; o < 16; o <<= 1) rs[r] += __shfl_xor_sync(0xffffffffu, rs[r], o);
    float part = 0.f;
#pragma unroll
    for (int r = 0; r < 4; ++r) {
        int ig = ibase + r;
        int tx_d = (ig & 127) >> 3;
        int srcLane = ((ty & 1) << 4) | tx_d;
        float s = __shfl_sync(0xffffffffu, sii[r], srcLane);
        if (tx == 0) part += logf(rs[r]) - s;
    }
    if (tx == 0) atomicAdd(acc, (LAM1 * 0.5f / (float)BATCH) * part);
}

// single intra loss via symmetry (tile pairs ta<=tb) — R9-proven body, per-matrix.
__global__ void __launch_bounds__(256) k_cl_intra1(const float* __restrict__ Pg,
                                                   float* __restrict__ rsp) {
    __shared__ float Pa[32 * 128];
    __shared__ float Pb[32 * 128];
    __shared__ float sm_col[16 * 128];
    int rem = blockIdx.x;
    int ta = 0;
    while (rem >= 16 - ta) { rem -= 16 - ta; ++ta; }
    int tb = ta + rem;
    int tid = threadIdx.x;
    int tx = tid & 15;
    int ty = tid >> 4;

    float av[8][8];
#pragma unroll
    for (int r = 0; r < 8; ++r)
#pragma unroll
        for (int c = 0; c < 8; ++c) av[r][c] = 0.f;

#pragma unroll
    for (int kc = 0; kc < 2; ++kc) {
        __syncthreads();
        for (int idx = tid; idx < 32 * 32; idx += 256) {
            int k = idx >> 5, c4 = idx & 31;
            const float* src = Pg + (size_t)(kc * 32 + k) * BATCH;
            *(float4*)(Pa + k * 128 + c4 * 4) = *(const float4*)(src + ta * 128 + c4 * 4);
            *(float4*)(Pb + k * 128 + c4 * 4) = *(const float4*)(src + tb * 128 + c4 * 4);
        }
        __syncthreads();
#pragma unroll 8
        for (int k = 0; k < 32; ++k) {
            float a[8], b[8];
            *(float4*)a       = *(const float4*)(Pa + k * 128 + ty * 8);
            *(float4*)(a + 4) = *(const float4*)(Pa + k * 128 + ty * 8 + 4);
            *(float4*)b       = *(const float4*)(Pb + k * 128 + tx * 8);
            *(float4*)(b + 4) = *(const float4*)(Pb + k * 128 + tx * 8 + 4);
#pragma unroll
            for (int r = 0; r < 8; ++r)
#pragma unroll
                for (int c = 0; c < 8; ++c) av[r][c] += a[r] * b[c];
        }
    }

    float rsum[8], csum[8];
#pragma unroll
    for (int r = 0; r < 8; ++r) rsum[r] = 0.f;
#pragma unroll
    for (int c = 0; c < 8; ++c) csum[c] = 0.f;
#pragma unroll
    for (int r = 0; r < 8; ++r)
#pragma unroll
        for (int c = 0; c < 8; ++c) {
            float e = __expf(av[r][c] * INVTAU);
            rsum[r] += e;
            csum[c] += e;
        }
#pragma unroll
    for (int r = 0; r < 8; ++r)
#pragma unroll
        for (int o = 1; o < 16; o <<= 1) rsum[r] += __shfl_xor_sync(0xffffffffu, rsum[r], o);
    if (tx == 0) {
#pragma unroll
        for (int r = 0; r < 8; ++r)
            atomicAdd(rsp + ta * 128 + ty * 8 + r, rsum[r]);
    }
    if (ta != tb) {
        __syncthreads();
        *(float4*)(sm_col + ty * 128 + tx * 8)     = *(float4*)csum;
        *(float4*)(sm_col + ty * 128 + tx * 8 + 4) = *(float4*)(csum + 4);
        __syncthreads();
        if (tid < 128) {
            float s = 0.f;
#pragma unroll
            for (int t = 0; t < 16; ++t) s += sm_col[t * 128 + tid];
            atomicAdd(rsp + tb * 128 + tid, s);
        }
    }
}

__global__ void k_cl_fin(float* __restrict__ rs, float* acc) {
    int i = blockIdx.x * blockDim.x + threadIdx.x;
    float part = 0.f;
    if (i < 6 * BATCH) {
        float v = rs[i];
        rs[i] = 0.f;
        part = logf(v) - INVTAU;
    }
    part = warp_sum(part);
    __shared__ float sm[8];
    if ((threadIdx.x & 31) == 0) sm[threadIdx.x >> 5] = part;
    __syncthreads();
    if (threadIdx.x == 0) {
        float tt = 0.f;
#pragma unroll
        for (int k = 0; k < 8; ++k) tt += sm[k];
        atomicAdd(acc, (LAM1 * 0.5f / (float)BATCH) * tt);
    }
}

__global__ void k_final(const float* __restrict__ acc, float* out, int out_size) {
    if (threadIdx.x == 0) {
        out[0] = -acc[0] / (float)BATCH + LAM2 * acc[1];
        if (out_size > 1) out[1] = acc[2];
    }
}

// ---------------- host orchestration ----------------
extern "C" void kernel_launch(void* const* d_in, const int* in_sizes, int n_in,
                              void* d_out, int out_size) {
    const float* uf  = (const float*)d_in[0];
    const float* bfe = (const float*)d_in[1];
    const float* itf = (const float*)d_in[2];
    const int*   ub_r = (const int*)d_in[3];
    const int*   ub_c = (const int*)d_in[4];
    const float* ub_v = (const float*)d_in[5];
    const int*   ui_r = (const int*)d_in[6];
    const int*   ui_c = (const int*)d_in[7];
    const float* ui_v = (const float*)d_in[8];
    const int*   bi_r = (const int*)d_in[9];
    const int*   bi_c = (const int*)d_in[10];
    const float* bi_v = (const float*)d_in[11];
    const int*   ba_r = (const int*)d_in[12];
    const int*   ba_c = (const int*)d_in[13];
    const float* ba_v = (const float*)d_in[14];
    const int*   ua_r = (const int*)d_in[15];
    const int*   ua_c = (const int*)d_in[16];
    const float* ua_v = (const float*)d_in[17];
    const float* n_UB  = (const float*)d_in[18];
    const float* n_UI  = (const float*)d_in[19];
    const float* n_BI  = (const float*)d_in[20];
    const float* n_aBI = (const float*)d_in[21];
    const float* n_aUI = (const float*)d_in[22];
    const int* users   = (const int*)d_in[23];
    const int* bundles = (const int*)d_in[24];

    int nUB = in_sizes[3];
    int nUI = in_sizes[6];
    int nBI = in_sizes[9];
    int nBA = in_sizes[12];
    int nUA = in_sizes[15];

    float *fUB, *tUB, *fUI, *tUI, *fBI, *tBI, *tAB, *tAU;
    float *pUB, *pUI, *pBI, *pUIb, *pBIu, *pP, *prs, *acc;
    cudaGetSymbolAddress((void**)&fUB, g_fUB);
    cudaGetSymbolAddress((void**)&tUB, g_tUB);
    cudaGetSymbolAddress((void**)&fUI, g_fUI);
    cudaGetSymbolAddress((void**)&tUI, g_tUI);
    cudaGetSymbolAddress((void**)&fBI, g_fBI);
    cudaGetSymbolAddress((void**)&tBI, g_tBI);
    cudaGetSymbolAddress((void**)&tAB, g_tAB);
    cudaGetSymbolAddress((void**)&tAU, g_tAU);
    cudaGetSymbolAddress((void**)&pUB, g_UB);
    cudaGetSymbolAddress((void**)&pUI, g_UI);
    cudaGetSymbolAddress((void**)&pBI, g_BI);
    cudaGetSymbolAddress((void**)&pUIb, g_UIb);
    cudaGetSymbolAddress((void**)&pBIu, g_BIu);
    cudaGetSymbolAddress((void**)&pP,  g_P);
    cudaGetSymbolAddress((void**)&prs, g_rs);
    cudaGetSymbolAddress((void**)&acc, g_acc);

    cudaStream_t s0 = 0;
    cudaStream_t s1 = g_sh.s1, s2 = g_sh.s2;

    cudaMemsetAsync(acc, 0, 4 * sizeof(float), s0);

    cudaEventRecord(g_sh.f, s0);
    cudaStreamWaitEvent(s1, g_sh.f, 0);
    cudaStreamWaitEvent(s2, g_sh.f, 0);

    auto spmm = [&](cudaStream_t st, const int* r, const int* c, const float* v,
                    int nE, const float* x, float* out) {
        long long thr = (long long)((nE + 3) / 4) * 16;
        int blocks = (int)((thr + 255) / 256);
        k_spmm<<<blocks, 256, 0, st>>>(r, c, v, x, out, nE);
    };

    auto propagate = [&](cudaStream_t st, float* feats, float* tmp,
                         const int* r, const int* c, const float* v, int nE,
                         const float* A, const float* Bf, int nA, int n,
                         const float* noise, float ups, float* outb) {
        int nd = n * D;
        k_init<<<(nd + 255) / 256, 256, 0, st>>>(A, Bf, nA, n, feats, outb);
        for (int l = 0; l < 2; ++l) {
            cudaMemsetAsync(tmp, 0, (size_t)nd * sizeof(float), st);
            spmm(st, r, c, v, nE, feats, tmp);
            k_prop_row<<<(n + 7) / 8, 256, 0, st>>>(tmp, noise + (size_t)l * nd, feats, outb, n, ups);
        }
    };

    int gb = (BATCH + 7) / 8;   // gather/bpr grid

    // s0: UB chain, then regularizer, then UB-dependent CL work (p0, p3)
    propagate(s0, fUB, tUB, ub_r, ub_c, ub_v, nUB, uf,  bfe, U_N, U_N + B_N, n_UB, 0.1f, pUB);
    k_sumsq<<<592, 256, 0, s0>>>(uf,  U_N * D, acc + 1);
    k_sumsq<<<592, 256, 0, s0>>>(bfe, B_N * D, acc + 1);
    k_sumsq<<<592, 256, 0, s0>>>(itf, I_N * D, acc + 1);
    k_gather1<<<gb, 256, 0, s0>>>(users,   1, pUB,                      pP + 0 * DB);
    k_gather1<<<gb, 256, 0, s0>>>(bundles, 2, pUB + (size_t)U_N * D,    pP + 3 * DB);
    k_cl_intra1<<<136, 256, 0, s0>>>(pP + 0 * DB, prs + 0 * BATCH);
    k_cl_intra1<<<136, 256, 0, s0>>>(pP + 3 * DB, prs + 3 * BATCH);

    // s1: UI chain, biagg -> UIb, then UI-dependent CL work (p1, p4)
    propagate(s1, fUI, tUI, ui_r, ui_c, ui_v, nUI, uf,  itf, U_N, U_N + I_N, n_UI, 0.1f, pUI);
    cudaMemsetAsync(tAB, 0, (size_t)B_N * D * sizeof(float), s1);
    spmm(s1, ba_r, ba_c, ba_v, nBA, pUI + (size_t)U_N * D, tAB);
    k_agg_row<<<(B_N + 7) / 8, 256, 0, s1>>>(tAB, n_aBI, pUIb, B_N, 0.1f);
    k_gather1<<<gb, 256, 0, s1>>>(users,   1, pUI,  pP + 1 * DB);
    k_cl_intra1<<<136, 256, 0, s1>>>(pP + 1 * DB, prs + 1 * BATCH);
    k_gather1<<<gb, 256, 0, s1>>>(bundles, 2, pUIb, pP + 4 * DB);
    k_cl_intra1<<<136, 256, 0, s1>>>(pP + 4 * DB, prs + 4 * BATCH);
    cudaEventRecord(g_sh.e1, s1);

    // s2: BI chain, uiagg -> BIu, then BI-dependent CL work (p5, p2)
    propagate(s2, fBI, tBI, bi_r, bi_c, bi_v, nBI, bfe, itf, B_N, B_N + I_N, n_BI, 0.1f, pBI);
    k_gather1<<<gb, 256, 0, s2>>>(bundles, 2, pBI,  pP + 5 * DB);
    k_cl_intra1<<<136, 256, 0, s2>>>(pP + 5 * DB, prs + 5 * BATCH);
    cudaMemsetAsync(tAU, 0, (size_t)U_N * D * sizeof(float), s2);
    spmm(s2, ua_r, ua_c, ua_v, nUA, pBI + (size_t)B_N * D, tAU);
    k_agg_row<<<(U_N + 7) / 8, 256, 0, s2>>>(tAU, n_aUI, pBIu, U_N, 0.1f);
    k_gather1<<<gb, 256, 0, s2>>>(users,   1, pBIu, pP + 2 * DB);
    k_cl_intra1<<<136, 256, 0, s2>>>(pP + 2 * DB, prs + 2 * BATCH);
    cudaEventRecord(g_sh.e2, s2);

    // join
    cudaStreamWaitEvent(s0, g_sh.e1, 0);
    cudaStreamWaitEvent(s0, g_sh.e2, 0);

    // BPR + inter losses + finish
    k_bpr<<<gb, 256, 0, s0>>>(users, bundles, pUI, pBIu, pUIb, pBI, acc);
    k_cl_inter<<<dim3(32, 6), 256, 0, s0>>>(pP, acc + 2);
    k_cl_fin<<<(6 * BATCH + 255) / 256, 256, 0, s0>>>(prs, acc + 2);

    k_final<<<1, 1, 0, s0>>>(acc, (float*)d_out, out_size);
}

// round 17
// speedup vs baseline: 1.6234x; 1.0061x over previous
#include <cuda_runtime.h>
#include <math.h>

#define U_N 50000
#define B_N 20000
#define I_N 100000
#define D 64
#define BATCH 2048
#define INVTAU 4.0f
#define LAM1 0.04f
#define LAM2 1e-5f
#define XI (1.0f/3.0f)
#define DB (D * BATCH)

// ---------------- static device workspace (no allocs allowed) ----------------
__device__ float g_fUB[(U_N + B_N) * D];
__device__ float g_tUB[(U_N + B_N) * D];
__device__ float g_fUI[(U_N + I_N) * D];
__device__ float g_tUI[(U_N + I_N) * D];
__device__ float g_fBI[(B_N + I_N) * D];
__device__ float g_tBI[(B_N + I_N) * D];
__device__ float g_tAB[B_N * D];             // biagg scratch (stream 1)
__device__ float g_tAU[U_N * D];             // uiagg scratch (stream 2)
__device__ float g_UB [(U_N + B_N) * D];
__device__ float g_UI [(U_N + I_N) * D];
__device__ float g_BI [(B_N + I_N) * D];
__device__ float g_UIb[B_N * D];
__device__ float g_BIu[U_N * D];
__device__ float g_P  [6 * DB];              // normalized CL matrices, k-major: [p][k][i]
__device__ float g_rs [6 * BATCH];           // intra row sums (zero-init; fin re-zeroes)
__device__ float g_acc[4];                   // 0: sum logsigmoid, 1: reg, 2: cl

__constant__ int c_pa[6] = {0,0,1,3,3,4};
__constant__ int c_pb[6] = {1,2,2,4,5,5};

// ---------------- static streams/events (created once) ----------------
namespace {
struct StreamHolder {
    cudaStream_t s1 = 0, s2 = 0;
    cudaEvent_t  f = 0, e0 = 0, e1 = 0, e2 = 0, t1 = 0, t2 = 0;
    StreamHolder() {
        cudaStreamCreateWithFlags(&s1, cudaStreamNonBlocking);
        cudaStreamCreateWithFlags(&s2, cudaStreamNonBlocking);
        cudaEventCreateWithFlags(&f,  cudaEventDisableTiming);
        cudaEventCreateWithFlags(&e0, cudaEventDisableTiming);
        cudaEventCreateWithFlags(&e1, cudaEventDisableTiming);
        cudaEventCreateWithFlags(&e2, cudaEventDisableTiming);
        cudaEventCreateWithFlags(&t1, cudaEventDisableTiming);
        cudaEventCreateWithFlags(&t2, cudaEventDisableTiming);
    }
};
StreamHolder g_sh;
}

// ---------------- small helpers ----------------
__device__ __forceinline__ float warp_sum(float v) {
#pragma unroll
    for (int o = 16; o; o >>= 1) v += __shfl_xor_sync(0xffffffffu, v, o);
    return v;
}
__device__ __forceinline__ float sgn(float x) {
    return (x > 0.f) ? 1.f : ((x < 0.f) ? -1.f : 0.f);
}
__device__ __forceinline__ void red4(float* p, float4 o) {
    asm volatile("red.global.add.v4.f32 [%0], {%1,%2,%3,%4};"
                 :: "l"(p), "f"(o.x), "f"(o.y), "f"(o.z), "f"(o.w) : "memory");
}

// ---------------- kernels ----------------

__global__ void k_init(const float* __restrict__ A, const float* __restrict__ Bf,
                       int nA, int n, float* feats, float* outb) {
    int i = blockIdx.x * blockDim.x + threadIdx.x;
    if (i >= n * D) return;
    float v = (i < nA * D) ? A[i] : Bf[i - nA * D];
    feats[i] = v;
    outb[i]  = v * XI;
}

// fp32 COO spmm: 16 threads/chunk, 4 edges/thread (MLP=4). Proven floor.
__global__ void k_spmm(const int* __restrict__ rows, const int* __restrict__ cols,
                       const float* __restrict__ vals, const float* __restrict__ x,
                       float* out, int nE) {
    int t = blockIdx.x * blockDim.x + threadIdx.x;
    int g = t >> 4;
    int c = t & 15;
    int e0 = g * 4;
    if (e0 >= nE) return;
    int nv = nE - e0;

    int   r[4], cc[4];
    float v[4];
    if (nv >= 4) {
        int4   r4 = __ldg((const int4*)(rows + e0));
        int4   c4 = __ldg((const int4*)(cols + e0));
        float4 v4 = __ldg((const float4*)(vals + e0));
        r[0]=r4.x; r[1]=r4.y; r[2]=r4.z; r[3]=r4.w;
        cc[0]=c4.x; cc[1]=c4.y; cc[2]=c4.z; cc[3]=c4.w;
        v[0]=v4.x; v[1]=v4.y; v[2]=v4.z; v[3]=v4.w;
    } else {
#pragma unroll
        for (int k = 0; k < 4; ++k) {
            int e = e0 + ((k < nv) ? k : (nv - 1));
            r[k]  = __ldg(rows + e);
            cc[k] = __ldg(cols + e);
            v[k]  = __ldg(vals + e);
        }
    }
    float4 a[4];
#pragma unroll
    for (int k = 0; k < 4; ++k)
        a[k] = __ldg((const float4*)(x + (size_t)cc[k] * D) + c);
#pragma unroll
    for (int k = 0; k < 4; ++k) {
        if (k < nv) {
            red4(out + (size_t)r[k] * D + c * 4,
                 make_float4(v[k]*a[k].x, v[k]*a[k].y, v[k]*a[k].z, v[k]*a[k].w));
        }
    }
}

__global__ void k_prop_row(const float* __restrict__ tmp, const float* __restrict__ noise,
                           float* feats, float* outb, int n, float ups) {
    int row = blockIdx.x * 8 + (threadIdx.x >> 5);
    int lane = threadIdx.x & 31;
    if (row >= n) return;
    size_t off = (size_t)row * D + lane * 2;
    float2 t  = *(const float2*)(tmp + off);
    float2 nz = *(const float2*)(noise + off);
    float ns = warp_sum(nz.x * nz.x + nz.y * nz.y);
    float ninv = ups / fmaxf(sqrtf(ns), 1e-12f);
    float fx = t.x + sgn(t.x) * nz.x * ninv;
    float fy = t.y + sgn(t.y) * nz.y * ninv;
    float fs = warp_sum(fx * fx + fy * fy);
    float finv = XI / fmaxf(sqrtf(fs), 1e-12f);
    float2 ob = *(float2*)(outb + off);
    ob.x += fx * finv;
    ob.y += fy * finv;
    *(float2*)(outb + off) = ob;
    *(float2*)(feats + off) = make_float2(fx, fy);
}

__global__ void k_agg_row(const float* __restrict__ tmp, const float* __restrict__ noise,
                          float* outb, int n, float ups) {
    int row = blockIdx.x * 8 + (threadIdx.x >> 5);
    int lane = threadIdx.x & 31;
    if (row >= n) return;
    size_t off = (size_t)row * D + lane * 2;
    float2 t  = *(const float2*)(tmp + off);
    float2 nz = *(const float2*)(noise + off);
    float ns = warp_sum(nz.x * nz.x + nz.y * nz.y);
    float ninv = ups / fmaxf(sqrtf(ns), 1e-12f);
    float fx = t.x + sgn(t.x) * nz.x * ninv;
    float fy = t.y + sgn(t.y) * nz.y * ninv;
    *(float2*)(outb + off) = make_float2(fx, fy);
}

__global__ void k_sumsq(const float* __restrict__ x, int n, float* acc) {
    float s = 0.f;
    for (int i = blockIdx.x * blockDim.x + threadIdx.x; i < n; i += gridDim.x * blockDim.x) {
        float v = x[i];
        s += v * v;
    }
    s = warp_sum(s);
    __shared__ float sm[8];
    if ((threadIdx.x & 31) == 0) sm[threadIdx.x >> 5] = s;
    __syncthreads();
    if (threadIdx.x == 0) {
        float tt = 0.f;
#pragma unroll
        for (int i = 0; i < 8; ++i) tt += sm[i];
        atomicAdd(acc, tt);
    }
}

__global__ void k_bpr(const int* __restrict__ users, const int* __restrict__ bundles,
                      const float* __restrict__ UIu, const float* __restrict__ BIu,
                      const float* __restrict__ UIb, const float* __restrict__ BIb,
                      float* acc) {
    int i = blockIdx.x * 8 + (threadIdx.x >> 5);
    int lane = threadIdx.x & 31;
    if (i >= BATCH) return;
    int u  = users[i];
    int bp = bundles[2 * i];
    int bn = bundles[2 * i + 1];
    size_t uo = (size_t)u * D + lane * 2;
    float2 a1 = *(const float2*)(UIu + uo);
    float2 a2 = *(const float2*)(BIu + uo);
    float ux = 0.5f * (a1.x + a2.x), uy = 0.5f * (a1.y + a2.y);
    size_t po = (size_t)bp * D + lane * 2;
    float2 p1 = *(const float2*)(UIb + po);
    float2 p2 = *(const float2*)(BIb + po);
    float px = 0.5f * (p1.x + p2.x), py = 0.5f * (p1.y + p2.y);
    size_t no = (size_t)bn * D + lane * 2;
    float2 q1 = *(const float2*)(UIb + no);
    float2 q2 = *(const float2*)(BIb + no);
    float qx = 0.5f * (q1.x + q2.x), qy = 0.5f * (q1.y + q2.y);
    float dp = warp_sum(ux * px + uy * py);
    float dn = warp_sum(ux * qx + uy * qy);
    if (lane == 0) {
        float x = dp - dn;
        float ls = (x >= 0.f) ? -log1pf(expf(-x)) : (x - log1pf(expf(x)));
        atomicAdd(acc, ls);
    }
}

// single-matrix gather + row-normalize into k-major dstP[k][i]
__global__ void k_gather1(const int* __restrict__ ids, int stride,
                          const float* __restrict__ src, float* __restrict__ dstP) {
    int i = blockIdx.x * 8 + (threadIdx.x >> 5);
    int lane = threadIdx.x & 31;
    if (i >= BATCH) return;
    int r0 = ids[i * stride];
    const float* s = src + (size_t)r0 * D;
    float2 v = *(const float2*)(s + lane * 2);
    float ss = warp_sum(v.x * v.x + v.y * v.y);
    float inv = 1.f / fmaxf(sqrtf(ss), 1e-12f);
    dstP[(size_t)(2 * lane) * BATCH + i]     = v.x * inv;
    dstP[(size_t)(2 * lane + 1) * BATCH + i] = v.y * inv;
}

// inter losses, pair indices [pbase, pbase+gridDim.y): S = P@Q^T/tau,
// loss_i = log(sum_j exp(S_ij)) - S_ii.  R13-proven body.
__global__ void __launch_bounds__(256) k_cl_inter(const float* __restrict__ P, float* acc,
                                                  int pbase) {
    __shared__ float Ps[64 * 64];
    __shared__ float Qs[64 * 128];
    int p  = pbase + blockIdx.y;
    int bi = blockIdx.x;
    int tid = threadIdx.x;
    int tx = tid & 15;
    int ty = tid >> 4;
    const float* Pg = P + (size_t)c_pa[p] * DB;
    const float* Qg = P + (size_t)c_pb[p] * DB;
    for (int idx = tid; idx < 64 * 16; idx += 256) {
        int k = idx >> 4, c4 = idx & 15;
        *(float4*)(Ps + k * 64 + c4 * 4) = *(const float4*)(Pg + (size_t)k * BATCH + bi * 64 + c4 * 4);
    }
    float rs[4] = {0.f, 0.f, 0.f, 0.f};
    float sii[4] = {0.f, 0.f, 0.f, 0.f};
    int ibase = bi * 64 + ty * 4;
    for (int jt = 0; jt < 16; ++jt) {
        __syncthreads();
        for (int idx = tid; idx < 64 * 32; idx += 256) {
            int k = idx >> 5, c4 = idx & 31;
            *(float4*)(Qs + k * 128 + c4 * 4) = *(const float4*)(Qg + (size_t)k * BATCH + jt * 128 + c4 * 4);
        }
        __syncthreads();
        float av[4][8];
#pragma unroll
        for (int r = 0; r < 4; ++r)
#pragma unroll
            for (int c = 0; c < 8; ++c) av[r][c] = 0.f;
#pragma unroll 8
        for (int k = 0; k < 64; ++k) {
            float a[4], b[8];
            *(float4*)a       = *(const float4*)(Ps + k * 64 + ty * 4);
            *(float4*)b       = *(const float4*)(Qs + k * 128 + tx * 8);
            *(float4*)(b + 4) = *(const float4*)(Qs + k * 128 + tx * 8 + 4);
#pragma unroll
            for (int r = 0; r < 4; ++r)
#pragma unroll
                for (int c = 0; c < 8; ++c) av[r][c] += a[r] * b[c];
        }
        int jbase = jt * 128 + tx * 8;
#pragma unroll
        for (int r = 0; r < 4; ++r) {
#pragma unroll
            for (int c = 0; c < 8; ++c) {
                float s = av[r][c] * INVTAU;
                if (jbase + c == ibase + r) sii[r] = s;
                rs[r] += __expf(s);
            }
        }
    }
#pragma unroll
    for (int r = 0; r < 4; ++r)
#pragma unroll
        for (int o = 1; o < 16; o <<= 1) rs[r] += __shfl_xor_sync(0xffffffffu, rs[r], o);
    float part = 0.f;
#pragma unroll
    for (int r = 0; r < 4; ++r) {
        int ig = ibase + r;
        int tx_d = (ig & 127) >> 3;
        int srcLane = ((ty & 1) << 4) | tx_d;
        float s = __shfl_sync(0xffffffffu, sii[r], srcLane);
        if (tx == 0) part += logf(rs[r]) - s;
    }
    if (tx == 0) atomicAdd(acc, (LAM1 * 0.5f / (float)BATCH) * part);
}

// single intra loss via symmetry (tile pairs ta<=tb) — R9-proven body, per-matrix.
__global__ void __launch_bounds__(256) k_cl_intra1(const float* __restrict__ Pg,
                                                   float* __restrict__ rsp) {
    __shared__ float Pa[32 * 128];
    __shared__ float Pb[32 * 128];
    __shared__ float sm_col[16 * 128];
    int rem = blockIdx.x;
    int ta = 0;
    while (rem >= 16 - ta) { rem -= 16 - ta; ++ta; }
    int tb = ta + rem;
    int tid = threadIdx.x;
    int tx = tid & 15;
    int ty = tid >> 4;

    float av[8][8];
#pragma unroll
    for (int r = 0; r < 8; ++r)
#pragma unroll
        for (int c = 0; c < 8; ++c) av[r][c] = 0.f;

#pragma unroll
    for (int kc = 0; kc < 2; ++kc) {
        __syncthreads();
        for (int idx = tid; idx < 32 * 32; idx += 256) {
            int k = idx >> 5, c4 = idx & 31;
            const float* src = Pg + (size_t)(kc * 32 + k) * BATCH;
            *(float4*)(Pa + k * 128 + c4 * 4) = *(const float4*)(src + ta * 128 + c4 * 4);
            *(float4*)(Pb + k * 128 + c4 * 4) = *(const float4*)(src + tb * 128 + c4 * 4);
        }
        __syncthreads();
#pragma unroll 8
        for (int k = 0; k < 32; ++k) {
            float a[8], b[8];
            *(float4*)a       = *(const float4*)(Pa + k * 128 + ty * 8);
            *(float4*)(a + 4) = *(const float4*)(Pa + k * 128 + ty * 8 + 4);
            *(float4*)b       = *(const float4*)(Pb + k * 128 + tx * 8);
            *(float4*)(b + 4) = *(const float4*)(Pb + k * 128 + tx * 8 + 4);
#pragma unroll
            for (int r = 0; r < 8; ++r)
#pragma unroll
                for (int c = 0; c < 8; ++c) av[r][c] += a[r] * b[c];
        }
    }

    float rsum[8], csum[8];
#pragma unroll
    for (int r = 0; r < 8; ++r) rsum[r] = 0.f;
#pragma unroll
    for (int c = 0; c < 8; ++c) csum[c] = 0.f;
#pragma unroll
    for (int r = 0; r < 8; ++r)
#pragma unroll
        for (int c = 0; c < 8; ++c) {
            float e = __expf(av[r][c] * INVTAU);
            rsum[r] += e;
            csum[c] += e;
        }
#pragma unroll
    for (int r = 0; r < 8; ++r)
#pragma unroll
        for (int o = 1; o < 16; o <<= 1) rsum[r] += __shfl_xor_sync(0xffffffffu, rsum[r], o);
    if (tx == 0) {
#pragma unroll
        for (int r = 0; r < 8; ++r)
            atomicAdd(rsp + ta * 128 + ty * 8 + r, rsum[r]);
    }
    if (ta != tb) {
        __syncthreads();
        *(float4*)(sm_col + ty * 128 + tx * 8)     = *(float4*)csum;
        *(float4*)(sm_col + ty * 128 + tx * 8 + 4) = *(float4*)(csum + 4);
        __syncthreads();
        if (tid < 128) {
            float s = 0.f;
#pragma unroll
            for (int t = 0; t < 16; ++t) s += sm_col[t * 128 + tid];
            atomicAdd(rsp + tb * 128 + tid, s);
        }
    }
}

__global__ void k_cl_fin(float* __restrict__ rs, float* acc) {
    int i = blockIdx.x * blockDim.x + threadIdx.x;
    float part = 0.f;
    if (i < 6 * BATCH) {
        float v = rs[i];
        rs[i] = 0.f;
        part = logf(v) - INVTAU;
    }
    part = warp_sum(part);
    __shared__ float sm[8];
    if ((threadIdx.x & 31) == 0) sm[threadIdx.x >> 5] = part;
    __syncthreads();
    if (threadIdx.x == 0) {
        float tt = 0.f;
#pragma unroll
        for (int k = 0; k < 8; ++k) tt += sm[k];
        atomicAdd(acc, (LAM1 * 0.5f / (float)BATCH) * tt);
    }
}

__global__ void k_final(const float* __restrict__ acc, float* out, int out_size) {
    if (threadIdx.x == 0) {
        out[0] = -acc[0] / (float)BATCH + LAM2 * acc[1];
        if (out_size > 1) out[1] = acc[2];
    }
}

// ---------------- host orchestration ----------------
extern "C" void kernel_launch(void* const* d_in, const int* in_sizes, int n_in,
                              void* d_out, int out_size) {
    const float* uf  = (const float*)d_in[0];
    const float* bfe = (const float*)d_in[1];
    const float* itf = (const float*)d_in[2];
    const int*   ub_r = (const int*)d_in[3];
    const int*   ub_c = (const int*)d_in[4];
    const float* ub_v = (const float*)d_in[5];
    const int*   ui_r = (const int*)d_in[6];
    const int*   ui_c = (const int*)d_in[7];
    const float* ui_v = (const float*)d_in[8];
    const int*   bi_r = (const int*)d_in[9];
    const int*   bi_c = (const int*)d_in[10];
    const float* bi_v = (const float*)d_in[11];
    const int*   ba_r = (const int*)d_in[12];
    const int*   ba_c = (const int*)d_in[13];
    const float* ba_v = (const float*)d_in[14];
    const int*   ua_r = (const int*)d_in[15];
    const int*   ua_c = (const int*)d_in[16];
    const float* ua_v = (const float*)d_in[17];
    const float* n_UB  = (const float*)d_in[18];
    const float* n_UI  = (const float*)d_in[19];
    const float* n_BI  = (const float*)d_in[20];
    const float* n_aBI = (const float*)d_in[21];
    const float* n_aUI = (const float*)d_in[22];
    const int* users   = (const int*)d_in[23];
    const int* bundles = (const int*)d_in[24];

    int nUB = in_sizes[3];
    int nUI = in_sizes[6];
    int nBI = in_sizes[9];
    int nBA = in_sizes[12];
    int nUA = in_sizes[15];

    float *fUB, *tUB, *fUI, *tUI, *fBI, *tBI, *tAB, *tAU;
    float *pUB, *pUI, *pBI, *pUIb, *pBIu, *pP, *prs, *acc;
    cudaGetSymbolAddress((void**)&fUB, g_fUB);
    cudaGetSymbolAddress((void**)&tUB, g_tUB);
    cudaGetSymbolAddress((void**)&fUI, g_fUI);
    cudaGetSymbolAddress((void**)&tUI, g_tUI);
    cudaGetSymbolAddress((void**)&fBI, g_fBI);
    cudaGetSymbolAddress((void**)&tBI, g_tBI);
    cudaGetSymbolAddress((void**)&tAB, g_tAB);
    cudaGetSymbolAddress((void**)&tAU, g_tAU);
    cudaGetSymbolAddress((void**)&pUB, g_UB);
    cudaGetSymbolAddress((void**)&pUI, g_UI);
    cudaGetSymbolAddress((void**)&pBI, g_BI);
    cudaGetSymbolAddress((void**)&pUIb, g_UIb);
    cudaGetSymbolAddress((void**)&pBIu, g_BIu);
    cudaGetSymbolAddress((void**)&pP,  g_P);
    cudaGetSymbolAddress((void**)&prs, g_rs);
    cudaGetSymbolAddress((void**)&acc, g_acc);

    cudaStream_t s0 = 0;
    cudaStream_t s1 = g_sh.s1, s2 = g_sh.s2;

    cudaMemsetAsync(acc, 0, 4 * sizeof(float), s0);

    cudaEventRecord(g_sh.f, s0);
    cudaStreamWaitEvent(s1, g_sh.f, 0);
    cudaStreamWaitEvent(s2, g_sh.f, 0);

    auto spmm = [&](cudaStream_t st, const int* r, const int* c, const float* v,
                    int nE, const float* x, float* out) {
        long long thr = (long long)((nE + 3) / 4) * 16;
        int blocks = (int)((thr + 255) / 256);
        k_spmm<<<blocks, 256, 0, st>>>(r, c, v, x, out, nE);
    };

    auto propagate = [&](cudaStream_t st, float* feats, float* tmp,
                         const int* r, const int* c, const float* v, int nE,
                         const float* A, const float* Bf, int nA, int n,
                         const float* noise, float ups, float* outb) {
        int nd = n * D;
        k_init<<<(nd + 255) / 256, 256, 0, st>>>(A, Bf, nA, n, feats, outb);
        for (int l = 0; l < 2; ++l) {
            cudaMemsetAsync(tmp, 0, (size_t)nd * sizeof(float), st);
            spmm(st, r, c, v, nE, feats, tmp);
            k_prop_row<<<(n + 7) / 8, 256, 0, st>>>(tmp, noise + (size_t)l * nd, feats, outb, n, ups);
        }
    };

    int gb = (BATCH + 7) / 8;   // gather/bpr grid

    // s0: UB chain, then regularizer, then UB-dependent CL work (p0, p3)
    propagate(s0, fUB, tUB, ub_r, ub_c, ub_v, nUB, uf,  bfe, U_N, U_N + B_N, n_UB, 0.1f, pUB);
    k_sumsq<<<592, 256, 0, s0>>>(uf,  U_N * D, acc + 1);
    k_sumsq<<<592, 256, 0, s0>>>(bfe, B_N * D, acc + 1);
    k_sumsq<<<592, 256, 0, s0>>>(itf, I_N * D, acc + 1);
    k_gather1<<<gb, 256, 0, s0>>>(users,   1, pUB,                      pP + 0 * DB);
    k_gather1<<<gb, 256, 0, s0>>>(bundles, 2, pUB + (size_t)U_N * D,    pP + 3 * DB);
    k_cl_intra1<<<136, 256, 0, s0>>>(pP + 0 * DB, prs + 0 * BATCH);
    k_cl_intra1<<<136, 256, 0, s0>>>(pP + 3 * DB, prs + 3 * BATCH);
    cudaEventRecord(g_sh.e0, s0);

    // s1: UI chain, biagg -> UIb, then UI-dependent CL work (p1, p4)
    propagate(s1, fUI, tUI, ui_r, ui_c, ui_v, nUI, uf,  itf, U_N, U_N + I_N, n_UI, 0.1f, pUI);
    cudaMemsetAsync(tAB, 0, (size_t)B_N * D * sizeof(float), s1);
    spmm(s1, ba_r, ba_c, ba_v, nBA, pUI + (size_t)U_N * D, tAB);
    k_agg_row<<<(B_N + 7) / 8, 256, 0, s1>>>(tAB, n_aBI, pUIb, B_N, 0.1f);
    k_gather1<<<gb, 256, 0, s1>>>(users,   1, pUI,  pP + 1 * DB);
    k_cl_intra1<<<136, 256, 0, s1>>>(pP + 1 * DB, prs + 1 * BATCH);
    k_gather1<<<gb, 256, 0, s1>>>(bundles, 2, pUIb, pP + 4 * DB);
    k_cl_intra1<<<136, 256, 0, s1>>>(pP + 4 * DB, prs + 4 * BATCH);
    cudaEventRecord(g_sh.e1, s1);

    // s2: BI chain, uiagg -> BIu, then BI-dependent CL work (p5, p2)
    propagate(s2, fBI, tBI, bi_r, bi_c, bi_v, nBI, bfe, itf, B_N, B_N + I_N, n_BI, 0.1f, pBI);
    k_gather1<<<gb, 256, 0, s2>>>(bundles, 2, pBI,  pP + 5 * DB);
    k_cl_intra1<<<136, 256, 0, s2>>>(pP + 5 * DB, prs + 5 * BATCH);
    cudaMemsetAsync(tAU, 0, (size_t)U_N * D * sizeof(float), s2);
    spmm(s2, ua_r, ua_c, ua_v, nUA, pBI + (size_t)B_N * D, tAU);
    k_agg_row<<<(U_N + 7) / 8, 256, 0, s2>>>(tAU, n_aUI, pBIu, U_N, 0.1f);
    k_gather1<<<gb, 256, 0, s2>>>(users,   1, pBIu, pP + 2 * DB);
    k_cl_intra1<<<136, 256, 0, s2>>>(pP + 2 * DB, prs + 2 * BATCH);
    cudaEventRecord(g_sh.e2, s2);

    // full join on ALL streams (everyone waits on the other two)
    cudaStreamWaitEvent(s0, g_sh.e1, 0);
    cudaStreamWaitEvent(s0, g_sh.e2, 0);
    cudaStreamWaitEvent(s1, g_sh.e0, 0);
    cudaStreamWaitEvent(s1, g_sh.e2, 0);
    cudaStreamWaitEvent(s2, g_sh.e0, 0);
    cudaStreamWaitEvent(s2, g_sh.e1, 0);

    // parallel tail: three concurrent (32,2) inter launches (192 blocks total,
    // same residency as one (32,6) launch); bpr and fin hide under them.
    k_bpr<<<gb, 256, 0, s0>>>(users, bundles, pUI, pBIu, pUIb, pBI, acc);
    k_cl_inter<<<dim3(32, 2), 256, 0, s0>>>(pP, acc + 2, 0);   // pairs 0,1
    k_cl_inter<<<dim3(32, 2), 256, 0, s1>>>(pP, acc + 2, 2);   // pairs 2,3
    cudaEventRecord(g_sh.t1, s1);
    k_cl_fin<<<(6 * BATCH + 255) / 256, 256, 0, s2>>>(prs, acc + 2);
    k_cl_inter<<<dim3(32, 2), 256, 0, s2>>>(pP, acc + 2, 4);   // pairs 4,5
    cudaEventRecord(g_sh.t2, s2);

    cudaStreamWaitEvent(s0, g_sh.t1, 0);
    cudaStreamWaitEvent(s0, g_sh.t2, 0);
    k_final<<<1, 1, 0, s0>>>(acc, (float*)d_out, out_size);
}